// round 1
// baseline (speedup 1.0000x reference)
#include <cuda_runtime.h>
#include <cuda_bf16.h>

// Problem constants (match reference)
#define HH 512
#define WW 512
#define RR 4
#define BB 2
#define PP 65536
#define CC 8
#define NPTS (BB * PP)
#define NPIX (BB * HH * WW)

__constant__ float c_znear = 0.1f;
__constant__ float c_zfar  = 10.0f;

// Scratch (static device globals — no allocation allowed).
// Accumulator layout per pixel: acc[3*pix+0] = {w_sum, wz_sum, ws_sum, pad}
//                               acc[3*pix+1] = {wf0..wf3}
//                               acc[3*pix+2] = {wf4..wf7}
__device__ float4       g_acc[NPIX * 3];
__device__ unsigned int g_zmin[NPIX];

// ---------------------------------------------------------------------------
__global__ void k_init() {
    int i = blockIdx.x * blockDim.x + threadIdx.x;
    if (i >= NPIX) return;
    g_zmin[i] = __float_as_uint(10.0f);          // ZFAR
    float4 z4 = make_float4(0.f, 0.f, 0.f, 0.f);
    g_acc[3 * i + 0] = z4;
    g_acc[3 * i + 1] = z4;
    g_acc[3 * i + 2] = z4;
}

// Shared footprint-validity math. MUST be bit-identical between the zmin and
// accum passes so zmin <= z holds for every fragment the accum pass keeps.
// Forced round-to-nearest, no FMA contraction, so both kernels compile to
// the same arithmetic.
__device__ __forceinline__ float frag_d2(int qx, int qy, float x, float y) {
    float qxn = __fadd_rn(__fmul_rn(2.0f, (float)qx) / 511.0f, -1.0f);
    float qyn = __fadd_rn(__fmul_rn(2.0f, (float)qy) / 511.0f, -1.0f);
    float dx = __fadd_rn(qxn, -x);
    float dy = __fadd_rn(qyn, -y);
    return __fadd_rn(__fmul_rn(dx, dx), __fmul_rn(dy, dy));
}

// ---------------------------------------------------------------------------
__global__ void k_zmin(const float* __restrict__ pts,
                       const float* __restrict__ mr_ptr) {
    int i = blockIdx.x * blockDim.x + threadIdx.x;
    if (i >= NPTS) return;
    float x = pts[3 * i + 0];
    float y = pts[3 * i + 1];
    float z = pts[3 * i + 2];
    if (!(z > 0.1f && z < 10.0f)) return;
    float mr = *mr_ptr;
    float r2 = mr * mr;
    int cx = (int)rintf((x + 1.0f) * 0.5f * 511.0f);
    int cy = (int)rintf((y + 1.0f) * 0.5f * 511.0f);
    unsigned zb = __float_as_uint(z);
    int base = (i / PP) * (HH * WW);

    for (int oy = -RR; oy <= RR; ++oy) {
        int qy = cy + oy;
        if (qy < 0 || qy >= HH) continue;
        int rowbase = base + qy * WW;
#pragma unroll
        for (int ox = -RR; ox <= RR; ++ox) {
            int qx = cx + ox;
            if (qx < 0 || qx >= WW) continue;
            float d2 = frag_d2(qx, qy, x, y);
            if (d2 <= r2) {
                atomicMin(&g_zmin[rowbase + qx], zb);
            }
        }
    }
}

// ---------------------------------------------------------------------------
__global__ void k_accum(const float* __restrict__ pts,
                        const float* __restrict__ feat,
                        const float* __restrict__ sig,
                        const float* __restrict__ mr_ptr) {
    int i = blockIdx.x * blockDim.x + threadIdx.x;
    if (i >= NPTS) return;
    float x = pts[3 * i + 0];
    float y = pts[3 * i + 1];
    float z = pts[3 * i + 2];
    if (!(z > 0.1f && z < 10.0f)) return;
    float mr = *mr_ptr;
    float r2 = mr * mr;
    float s  = sig[i];
    float inv2s2 = 1.0f / (2.0f * s * s);

    const float4* f4 = (const float4*)feat;
    float4 fa = f4[2 * i + 0];
    float4 fb = f4[2 * i + 1];

    int cx = (int)rintf((x + 1.0f) * 0.5f * 511.0f);
    int cy = (int)rintf((y + 1.0f) * 0.5f * 511.0f);
    int base = (i / PP) * (HH * WW);

    for (int oy = -RR; oy <= RR; ++oy) {
        int qy = cy + oy;
        if (qy < 0 || qy >= HH) continue;
        int rowbase = base + qy * WW;
#pragma unroll
        for (int ox = -RR; ox <= RR; ++ox) {
            int qx = cx + ox;
            if (qx < 0 || qx >= WW) continue;
            float d2 = frag_d2(qx, qy, x, y);
            if (d2 <= r2) {
                int pix = rowbase + qx;
                float ws = __expf(-d2 * inv2s2);
                float zmin = __uint_as_float(g_zmin[pix]);
                // GAMMA = 0.5 -> 1/GAMMA = 2
                float w = ws * __expf(-(z - zmin) * 2.0f);
                float4 v0 = make_float4(w, w * z, ws, 0.0f);
                float4 v1 = make_float4(w * fa.x, w * fa.y, w * fa.z, w * fa.w);
                float4 v2 = make_float4(w * fb.x, w * fb.y, w * fb.z, w * fb.w);
                atomicAdd(&g_acc[3 * pix + 0], v0);
                atomicAdd(&g_acc[3 * pix + 1], v1);
                atomicAdd(&g_acc[3 * pix + 2], v2);
            }
        }
    }
}

// ---------------------------------------------------------------------------
// Output layout: [color (B,H,W,C)] [depth (B,H,W)] [mask (B,H,W)], all f32.
__global__ void k_final(float* __restrict__ out) {
    int i = blockIdx.x * blockDim.x + threadIdx.x;
    if (i >= NPIX) return;
    float4 a0 = g_acc[3 * i + 0];
    float4 a1 = g_acc[3 * i + 1];
    float4 a2 = g_acc[3 * i + 2];
    float denom = a0.x + 1e-8f;
    float inv = 1.0f / denom;

    float4* col = (float4*)(out);
    float4 c0 = make_float4(a1.x * inv, a1.y * inv, a1.z * inv, a1.w * inv);
    float4 c1 = make_float4(a2.x * inv, a2.y * inv, a2.z * inv, a2.w * inv);
    col[2 * i + 0] = c0;
    col[2 * i + 1] = c1;

    out[NPIX * CC + i]        = a0.y * inv;                 // depth
    out[NPIX * CC + NPIX + i] = 1.0f - expf(-a0.z);         // mask
}

// ---------------------------------------------------------------------------
extern "C" void kernel_launch(void* const* d_in, const int* in_sizes, int n_in,
                              void* d_out, int out_size) {
    const float* pts  = (const float*)d_in[0];  // [B,P,3]
    const float* feat = (const float*)d_in[1];  // [B,P,8]
    const float* sig  = (const float*)d_in[2];  // [B,P]
    const float* mr   = (const float*)d_in[3];  // scalar
    float* out = (float*)d_out;

    k_init<<<(NPIX + 255) / 256, 256>>>();
    k_zmin<<<(NPTS + 127) / 128, 128>>>(pts, mr);
    k_accum<<<(NPTS + 127) / 128, 128>>>(pts, feat, sig, mr);
    k_final<<<(NPIX + 255) / 256, 256>>>(out);
}

// round 2
// speedup vs baseline: 1.2300x; 1.2300x over previous
#include <cuda_runtime.h>
#include <cuda_bf16.h>

// Problem constants (match reference)
#define HH 512
#define WW 512
#define RR 4
#define BB 2
#define PP 65536
#define CC 8
#define NPTS (BB * PP)
#define NPIX (BB * HH * WW)

// Scratch (static device globals — zero-initialized at module load; k_final
// re-zeroes after reading so every graph replay starts from zeros).
// Accumulator layout per pixel: acc[3*pix+0] = {w_sum, wz_sum, ws_sum, pad}
//                               acc[3*pix+1] = {wf0..wf3}
//                               acc[3*pix+2] = {wf4..wf7}
__device__ float4 g_acc[NPIX * 3];

// ---------------------------------------------------------------------------
// Single scatter pass. Stabilizer-free weights: w' = ws * exp(-2z).
// color/depth ratios are mathematically identical to the reference's
// zmin-stabilized softmax (the exp(2*zmin) factor cancels); the EPS term's
// influence is bounded by 1e-8 * e^8 ~ 3e-5 relative, far below tolerance.
// Cull arithmetic (qxn/qyn/d2) kept bit-identical to the R1 passing kernel.
__global__ void __launch_bounds__(256) k_accum(
        const float* __restrict__ pts,
        const float* __restrict__ feat,
        const float* __restrict__ sig,
        const float* __restrict__ mr_ptr) {
    int i = blockIdx.x * blockDim.x + threadIdx.x;   // NPTS divisible by 256
    float x = pts[3 * i + 0];
    float y = pts[3 * i + 1];
    float z = pts[3 * i + 2];
    if (!(z > 0.1f && z < 10.0f)) return;

    float mr = *mr_ptr;
    float r2 = mr * mr;
    float s  = sig[i];
    float inv2s2 = 1.0f / (2.0f * s * s);
    float ez = __expf(-2.0f * z);                    // GAMMA = 0.5 -> factor 2

    const float4* f4 = (const float4*)feat;
    float4 fa = f4[2 * i + 0];
    float4 fb = f4[2 * i + 1];

    int cx = (int)rintf((x + 1.0f) * 0.5f * 511.0f);
    int cy = (int)rintf((y + 1.0f) * 0.5f * 511.0f);
    int base = (i >= PP) ? (HH * WW) : 0;

    // Precompute per-column dx^2 and in-bounds mask (bit-identical math to R1).
    float dx2c[2 * RR + 1];
    unsigned colmask = 0;
#pragma unroll
    for (int k = 0; k < 2 * RR + 1; ++k) {
        int qx = cx + k - RR;
        float qxn = __fadd_rn(__fmul_rn(2.0f, (float)qx) / 511.0f, -1.0f);
        float dx = __fadd_rn(qxn, -x);
        dx2c[k] = __fmul_rn(dx, dx);
        if (qx >= 0 && qx < WW) colmask |= (1u << k);
    }

    for (int j = 0; j < 2 * RR + 1; ++j) {
        int qy = cy + j - RR;
        if (qy < 0 || qy >= HH) continue;
        float qyn = __fadd_rn(__fmul_rn(2.0f, (float)qy) / 511.0f, -1.0f);
        float dy = __fadd_rn(qyn, -y);
        float dy2 = __fmul_rn(dy, dy);
        int rowbase = base + qy * WW + cx - RR;
#pragma unroll
        for (int k = 0; k < 2 * RR + 1; ++k) {
            float d2 = __fadd_rn(dx2c[k], dy2);
            if (((colmask >> k) & 1u) && d2 <= r2) {
                float ws = __expf(-d2 * inv2s2);
                float w  = ws * ez;
                float4* a = &g_acc[3 * (rowbase + k)];
                atomicAdd(&a[0], make_float4(w, w * z, ws, 0.0f));
                atomicAdd(&a[1], make_float4(w * fa.x, w * fa.y, w * fa.z, w * fa.w));
                atomicAdd(&a[2], make_float4(w * fb.x, w * fb.y, w * fb.z, w * fb.w));
            }
        }
    }
}

// ---------------------------------------------------------------------------
// Output layout: [color (B,H,W,C)] [depth (B,H,W)] [mask (B,H,W)], all f32.
// Also re-zeroes the accumulators for the next graph replay.
__global__ void __launch_bounds__(256) k_final(float* __restrict__ out) {
    int i = blockIdx.x * blockDim.x + threadIdx.x;   // NPIX divisible by 256
    float4 a0 = g_acc[3 * i + 0];
    float4 a1 = g_acc[3 * i + 1];
    float4 a2 = g_acc[3 * i + 2];
    float4 zz = make_float4(0.f, 0.f, 0.f, 0.f);
    g_acc[3 * i + 0] = zz;
    g_acc[3 * i + 1] = zz;
    g_acc[3 * i + 2] = zz;

    float inv = (a0.x > 0.0f) ? (1.0f / a0.x) : 0.0f;

    float4* col = (float4*)out;
    col[2 * i + 0] = make_float4(a1.x * inv, a1.y * inv, a1.z * inv, a1.w * inv);
    col[2 * i + 1] = make_float4(a2.x * inv, a2.y * inv, a2.z * inv, a2.w * inv);

    out[NPIX * CC + i]        = a0.y * inv;             // depth
    out[NPIX * CC + NPIX + i] = 1.0f - expf(-a0.z);     // mask
}

// ---------------------------------------------------------------------------
extern "C" void kernel_launch(void* const* d_in, const int* in_sizes, int n_in,
                              void* d_out, int out_size) {
    const float* pts  = (const float*)d_in[0];  // [B,P,3]
    const float* feat = (const float*)d_in[1];  // [B,P,8]
    const float* sig  = (const float*)d_in[2];  // [B,P]
    const float* mr   = (const float*)d_in[3];  // scalar
    float* out = (float*)d_out;

    k_accum<<<NPTS / 256, 256>>>(pts, feat, sig, mr);
    k_final<<<NPIX / 256, 256>>>(out);
}